// round 2
// baseline (speedup 1.0000x reference)
#include <cuda_runtime.h>
#include <cstdint>

// Shapes fixed by the problem: B=32, N=4096, D=512.
#define BB 32
#define NN 4096
#define DD 512

// Scratch (allocation-free rule: __device__ globals)
__device__ float g_attn[BB * NN];

// ---------------------------------------------------------------------------
// Kernel 1: cosine similarity + threshold per key row.
// grid = (N/8, B), block = 256 (8 warps, one warp per key row).
// Reads the full 256 MB key tensor exactly once — DRAM-bound, dominates
// runtime. Query staged in SMEM; its norm computed per-block (cheap,
// removes a separate kernel).
// ---------------------------------------------------------------------------
__global__ void __launch_bounds__(256) attn_kernel(
    const float* __restrict__ key,
    const float* __restrict__ query,
    const unsigned char* __restrict__ mask)
{
    int b = blockIdx.y;
    int warp = threadIdx.x >> 5;
    int lane = threadIdx.x & 31;

    __shared__ float4 sq[DD / 4];   // 2 KB
    __shared__ float  s_wsum[8];
    __shared__ float  s_qnorm;

    const float4* q4 = reinterpret_cast<const float4*>(query + (size_t)b * DD);
    if (threadIdx.x < DD / 4) sq[threadIdx.x] = q4[threadIdx.x];
    __syncthreads();

    // ---- per-block query norm (deterministic tree reduce) ----
    {
        float qs = 0.f;
        if (threadIdx.x < DD / 4) {
            float4 q = sq[threadIdx.x];
            qs = q.x * q.x + q.y * q.y + q.z * q.z + q.w * q.w;
        }
#pragma unroll
        for (int o = 16; o; o >>= 1) qs += __shfl_xor_sync(0xFFFFFFFFu, qs, o);
        if (lane == 0) s_wsum[warp] = qs;
        __syncthreads();
        if (threadIdx.x == 0)
            s_qnorm = sqrtf(s_wsum[0] + s_wsum[1] + s_wsum[2] + s_wsum[3]);
        __syncthreads();
    }

    int n = blockIdx.x * 8 + warp;
    const float4* k4 =
        reinterpret_cast<const float4*>(key + ((size_t)b * NN + n) * DD);

    float dot = 0.f, ss = 0.f;
#pragma unroll
    for (int j = 0; j < 4; j++) {
        float4 k = __ldcs(&k4[lane + 32 * j]);  // streaming: touched once
        float4 q = sq[lane + 32 * j];
        dot += k.x * q.x + k.y * q.y + k.z * q.z + k.w * q.w;
        ss  += k.x * k.x + k.y * k.y + k.z * k.z + k.w * k.w;
    }
#pragma unroll
    for (int o = 16; o; o >>= 1) {
        dot += __shfl_xor_sync(0xFFFFFFFFu, dot, o);
        ss  += __shfl_xor_sync(0xFFFFFFFFu, ss, o);
    }

    if (lane == 0) {
        float denom = fmaxf(s_qnorm * sqrtf(ss), 1e-8f);
        float a = dot / denom;
        if (mask[(size_t)b * NN + n]) a = 0.f;
        if (a < 0.9f) a = 0.f;
        g_attn[(size_t)b * NN + n] = a;
    }
}

// ---------------------------------------------------------------------------
// Kernel 2: deterministic per-batch compaction of nonzero attn + sparse
// gather over value. grid = B, block = 512 (thread t owns output dim t).
// Sparsity (~8/4096 rows survive) turns a 256 MB value read into ~0.5 MB.
// Compaction uses ballot+scan (index order preserved, fully deterministic).
// ---------------------------------------------------------------------------
__global__ void __launch_bounds__(512) gather_kernel(
    const float* __restrict__ value,
    float* __restrict__ out)
{
    int b    = blockIdx.x;
    int tid  = threadIdx.x;
    int wid  = tid >> 5;
    int lane = tid & 31;

    __shared__ int   s_idx[NN];    // worst-case dense
    __shared__ float s_val[NN];
    __shared__ int   s_warpoff[16];
    __shared__ int   s_cnt;
    __shared__ float s_wsum[16];
    __shared__ float s_inv;

    if (tid == 0) s_cnt = 0;
    __syncthreads();

    float sum = 0.f;
#pragma unroll
    for (int c = 0; c < NN / 512; c++) {
        int n = c * 512 + tid;
        float a = g_attn[(size_t)b * NN + n];
        bool p = (a != 0.f);
        sum += a;  // a==0 when !p

        unsigned m = __ballot_sync(0xFFFFFFFFu, p);
        int rank = __popc(m & ((1u << lane) - 1u));
        if (lane == 0) s_warpoff[wid] = __popc(m);  // temp: warp counts
        __syncthreads();
        if (tid == 0) {
            int acc = s_cnt;
#pragma unroll
            for (int i = 0; i < 16; i++) {
                int w = s_warpoff[i];
                s_warpoff[i] = acc;
                acc += w;
            }
            s_cnt = acc;
        }
        __syncthreads();
        if (p) {
            int pos = s_warpoff[wid] + rank;
            s_idx[pos] = n;
            s_val[pos] = a;
        }
        __syncthreads();  // protect s_warpoff before next chunk
    }

    // deterministic block sum
#pragma unroll
    for (int o = 16; o; o >>= 1) sum += __shfl_xor_sync(0xFFFFFFFFu, sum, o);
    if (lane == 0) s_wsum[wid] = sum;
    __syncthreads();
    if (tid == 0) {
        float t = 0.f;
#pragma unroll
        for (int i = 0; i < 16; i++) t += s_wsum[i];
        s_inv = 1.f / (t + 1e-8f);
    }
    __syncthreads();

    int cnt = s_cnt;
    float inv = s_inv;
    int d = tid;
    float acc = 0.f;
    for (int j = 0; j < cnt; j++) {
        acc += s_val[j] * value[((size_t)b * NN + s_idx[j]) * DD + d];
    }
    out[(size_t)b * DD + d] = acc * inv;
}

// ---------------------------------------------------------------------------
extern "C" void kernel_launch(void* const* d_in, const int* in_sizes, int n_in,
                              void* d_out, int out_size) {
    const float* query        = (const float*)d_in[0];
    const float* key          = (const float*)d_in[1];
    const float* value        = (const float*)d_in[2];
    const unsigned char* mask = (const unsigned char*)d_in[3];
    float* out                = (float*)d_out;

    attn_kernel<<<dim3(NN / 8, BB), 256>>>(key, query, mask);
    gather_kernel<<<BB, 512>>>(value, out);
}

// round 13
// speedup vs baseline: 1.0484x; 1.0484x over previous
#include <cuda_runtime.h>
#include <cstdint>

// Shapes fixed by the problem: B=32, N=4096, D=512.
#define BB 32
#define NN 4096
#define DD 512

// Scratch (allocation-free rule: __device__ globals)
__device__ float g_attn[BB * NN];

// ---------------------------------------------------------------------------
// Kernel 1: cosine similarity + threshold per key row.  [UNCHANGED — measured
// at the HBM roofline: ~39us for the mandatory 256 MB key read]
// grid = (N/8, B), block = 256 (8 warps, one warp per key row).
// ---------------------------------------------------------------------------
__global__ void __launch_bounds__(256) attn_kernel(
    const float* __restrict__ key,
    const float* __restrict__ query,
    const unsigned char* __restrict__ mask)
{
    int b = blockIdx.y;
    int warp = threadIdx.x >> 5;
    int lane = threadIdx.x & 31;

    __shared__ float4 sq[DD / 4];   // 2 KB
    __shared__ float  s_wsum[8];
    __shared__ float  s_qnorm;

    const float4* q4 = reinterpret_cast<const float4*>(query + (size_t)b * DD);
    if (threadIdx.x < DD / 4) sq[threadIdx.x] = q4[threadIdx.x];
    __syncthreads();

    // per-block query norm (deterministic tree reduce)
    {
        float qs = 0.f;
        if (threadIdx.x < DD / 4) {
            float4 q = sq[threadIdx.x];
            qs = q.x * q.x + q.y * q.y + q.z * q.z + q.w * q.w;
        }
#pragma unroll
        for (int o = 16; o; o >>= 1) qs += __shfl_xor_sync(0xFFFFFFFFu, qs, o);
        if (lane == 0) s_wsum[warp] = qs;
        __syncthreads();
        if (threadIdx.x == 0)
            s_qnorm = sqrtf(s_wsum[0] + s_wsum[1] + s_wsum[2] + s_wsum[3]);
        __syncthreads();
    }

    int n = blockIdx.x * 8 + warp;
    const float4* k4 =
        reinterpret_cast<const float4*>(key + ((size_t)b * NN + n) * DD);

    float dot = 0.f, ss = 0.f;
#pragma unroll
    for (int j = 0; j < 4; j++) {
        float4 k = __ldcs(&k4[lane + 32 * j]);  // streaming: touched once
        float4 q = sq[lane + 32 * j];
        dot += k.x * q.x + k.y * q.y + k.z * q.z + k.w * q.w;
        ss  += k.x * k.x + k.y * k.y + k.z * k.z + k.w * k.w;
    }
#pragma unroll
    for (int o = 16; o; o >>= 1) {
        dot += __shfl_xor_sync(0xFFFFFFFFu, dot, o);
        ss  += __shfl_xor_sync(0xFFFFFFFFu, ss, o);
    }

    if (lane == 0) {
        float denom = fmaxf(s_qnorm * sqrtf(ss), 1e-8f);
        float a = dot / denom;
        if (mask[(size_t)b * NN + n]) a = 0.f;
        if (a < 0.9f) a = 0.f;
        g_attn[(size_t)b * NN + n] = a;
    }
}

// ---------------------------------------------------------------------------
// Kernel 2: compaction + sparse gather, rebuilt for latency.
// grid = (B, 4), block = 128.  Block (b, g) computes out dims [128g, 128g+128).
//
// Compaction: thread t owns indices [32t, 32t+32) (8 x float4 from L2, MLP=8),
// per-thread count/sum, single block scan -> index-ordered, deterministic,
// atomic-free, 2 syncs.
// Gather: value rows loaded 8-wide per iteration (MLP=8) so DRAM latency is
// paid once per 8 surviving rows, not once per row.
// ---------------------------------------------------------------------------
__global__ void __launch_bounds__(128) gather_kernel(
    const float* __restrict__ value,
    float* __restrict__ out)
{
    int b    = blockIdx.x;
    int tid  = threadIdx.x;
    int wid  = tid >> 5;
    int lane = tid & 31;

    __shared__ int   s_idx[NN];     // worst-case dense (16 KB)
    __shared__ float s_val[NN];     // (16 KB)
    __shared__ int   s_wtot[4];
    __shared__ float s_wsum[4];
    __shared__ int   s_cnt;
    __shared__ float s_inv;

    // ---- per-thread pass over 32 contiguous attn entries ----
    const float4* a4 = reinterpret_cast<const float4*>(g_attn + (size_t)b * NN)
                       + tid * 8;
    float av[32];
    float sum = 0.f;
    int   count = 0;
#pragma unroll
    for (int j = 0; j < 8; j++) {
        float4 v = a4[j];                    // independent: MLP=8
        av[j * 4 + 0] = v.x; av[j * 4 + 1] = v.y;
        av[j * 4 + 2] = v.z; av[j * 4 + 3] = v.w;
    }
#pragma unroll
    for (int e = 0; e < 32; e++) {
        sum += av[e];                        // zero entries contribute 0
        count += (av[e] != 0.f);
    }

    // ---- block exclusive scan of counts (deterministic) ----
    int inc = count;
#pragma unroll
    for (int o = 1; o < 32; o <<= 1) {
        int v = __shfl_up_sync(0xFFFFFFFFu, inc, o);
        if (lane >= o) inc += v;
    }
    float wsum = sum;
#pragma unroll
    for (int o = 16; o; o >>= 1) wsum += __shfl_xor_sync(0xFFFFFFFFu, wsum, o);
    if (lane == 31) s_wtot[wid] = inc;
    if (lane == 0)  s_wsum[wid] = wsum;
    __syncthreads();
    if (tid == 0) {
        int acc = 0;
#pragma unroll
        for (int i = 0; i < 4; i++) { int w = s_wtot[i]; s_wtot[i] = acc; acc += w; }
        s_cnt = acc;
        s_inv = 1.f / (s_wsum[0] + s_wsum[1] + s_wsum[2] + s_wsum[3] + 1e-8f);
    }
    __syncthreads();

    // ---- write survivors in index order ----
    int pos = s_wtot[wid] + (inc - count);
#pragma unroll
    for (int e = 0; e < 32; e++) {
        if (av[e] != 0.f) {
            s_idx[pos] = tid * 32 + e;
            s_val[pos] = av[e];
            pos++;
        }
    }
    __syncthreads();

    // ---- pipelined sparse gather over value ----
    int cnt = s_cnt;
    float inv = s_inv;
    int d = blockIdx.y * 128 + tid;
    const float* vb = value + (size_t)b * NN * DD + d;

    float acc = 0.f;
    for (int j0 = 0; j0 < cnt; j0 += 8) {
        float aa[8], vv[8];
#pragma unroll
        for (int u = 0; u < 8; u++) {        // 8 loads in flight before any FFMA
            int j = j0 + u;
            bool p = (j < cnt);
            int idx = p ? s_idx[j] : 0;      // speculation-safe address (0 valid)
            aa[u] = p ? s_val[j] : 0.f;
            vv[u] = p ? vb[(size_t)idx * DD] : 0.f;
        }
#pragma unroll
        for (int u = 0; u < 8; u++) acc += aa[u] * vv[u];
    }
    out[(size_t)b * DD + d] = acc * inv;
}

// ---------------------------------------------------------------------------
extern "C" void kernel_launch(void* const* d_in, const int* in_sizes, int n_in,
                              void* d_out, int out_size) {
    const float* query        = (const float*)d_in[0];
    const float* key          = (const float*)d_in[1];
    const float* value        = (const float*)d_in[2];
    const unsigned char* mask = (const unsigned char*)d_in[3];
    float* out                = (float*)d_out;

    attn_kernel<<<dim3(NN / 8, BB), 256>>>(key, query, mask);
    gather_kernel<<<dim3(BB, 4), 128>>>(value, out);
}